// round 6
// baseline (speedup 1.0000x reference)
#include <cuda_runtime.h>
#include <cuda_bf16.h>
#include <cstdint>

// Problem constants (fixed shapes)
#define B_    240
#define S_    64
#define H_    768
#define NH_   12
#define HD_   64
#define L0_   384
#define L1_   128
#define LT_   576          // L0+L1+S
#define BS_   8            // cache0 batch = 240/30
#define OUTSZ (B_*S_*H_)   // 11796480

// scratch: q in [B, nh, S, hd] fp32; packed bf16 hi/lo pair arrays
__device__ float g_q[B_ * NH_ * S_ * HD_];
__device__ uint32_t g_Ah[15360 * 384];        // hidden hi, pairs along k
__device__ uint32_t g_Al[15360 * 384];        // hidden lo
__device__ uint32_t g_Wh[3 * 768 * 384];      // Wq|Wk|Wv hi
__device__ uint32_t g_Wl[3 * 768 * 384];      // lo

// ---------------------------------------------------------------------------
// helpers
// ---------------------------------------------------------------------------
__device__ __forceinline__ uint32_t f2tf(float f) {
    uint32_t r;
    asm("cvt.rna.tf32.f32 %0, %1;" : "=r"(r) : "f"(f));
    return r;
}
__device__ __forceinline__ uint32_t packbf2(float x, float y) {
    __nv_bfloat162 h = __floats2bfloat162_rn(x, y);   // .x = x (low bits)
    return *reinterpret_cast<uint32_t*>(&h);
}

// D(16x8,f32) += A(16x8,tf32) * B(8x8,tf32)
__device__ __forceinline__ void mma8(float* d, const uint32_t* a, const uint32_t* b) {
    asm volatile(
        "mma.sync.aligned.m16n8k8.row.col.f32.tf32.tf32.f32 "
        "{%0,%1,%2,%3}, {%4,%5,%6,%7}, {%8,%9}, {%0,%1,%2,%3};"
        : "+f"(d[0]), "+f"(d[1]), "+f"(d[2]), "+f"(d[3])
        : "r"(a[0]), "r"(a[1]), "r"(a[2]), "r"(a[3]), "r"(b[0]), "r"(b[1]));
}
// D(16x8,f32) += A(16x16,bf16) * B(16x8,bf16)
__device__ __forceinline__ void mma16(float* d, const uint32_t* a, const uint32_t* b) {
    asm volatile(
        "mma.sync.aligned.m16n8k16.row.col.f32.bf16.bf16.f32 "
        "{%0,%1,%2,%3}, {%4,%5,%6,%7}, {%8,%9}, {%0,%1,%2,%3};"
        : "+f"(d[0]), "+f"(d[1]), "+f"(d[2]), "+f"(d[3])
        : "r"(a[0]), "r"(a[1]), "r"(a[2]), "r"(a[3]), "r"(b[0]), "r"(b[1]));
}

// ===========================================================================
// Kernel 0: prepack fp32 -> split bf16 (hi + lo), pairs packed along k.
// Covers hidden (2,949,120 float4) then Wq,Wk,Wv (147,456 float4 each).
// ===========================================================================
#define NF4_HID 2949120
#define NF4_W   147456
#define NF4_TOT (NF4_HID + 3 * NF4_W)

__global__ __launch_bounds__(256) void prepack_kernel(
    const float* __restrict__ hidden,
    const float* __restrict__ Wq,
    const float* __restrict__ Wk,
    const float* __restrict__ Wv)
{
    int f4 = blockIdx.x * 256 + threadIdx.x;
    if (f4 >= NF4_TOT) return;
    const float* src;
    uint32_t *dh, *dl;
    int off;
    if (f4 < NF4_HID) {
        src = hidden; off = f4; dh = g_Ah; dl = g_Al;
    } else {
        int w = f4 - NF4_HID;
        int sel = w / NF4_W;
        off = w - sel * NF4_W;
        src = (sel == 0) ? Wq : (sel == 1) ? Wk : Wv;
        dh = g_Wh + (size_t)sel * (768 * 384);
        dl = g_Wl + (size_t)sel * (768 * 384);
    }
    float4 v = ((const float4*)src)[off];
    uint32_t h0 = packbf2(v.x, v.y);
    uint32_t h1 = packbf2(v.z, v.w);
    __nv_bfloat162 hb0 = *reinterpret_cast<__nv_bfloat162*>(&h0);
    __nv_bfloat162 hb1 = *reinterpret_cast<__nv_bfloat162*>(&h1);
    uint32_t l0 = packbf2(v.x - __low2float(hb0), v.y - __high2float(hb0));
    uint32_t l1 = packbf2(v.z - __low2float(hb1), v.w - __high2float(hb1));
    ((uint2*)dh)[off] = make_uint2(h0, h1);
    ((uint2*)dl)[off] = make_uint2(l0, l1);
}

// ===========================================================================
// Kernel 1: QKV projection via split-bf16 m16n8k16 mma.sync.
// C[15360,768] = hidden @ W^T + bias -> [B, nh, S, hd] layout.
// 128x128 CTA tile, BK=32 floats (2 k16 groups), 256 thr (8 warps, 64x32).
// D += Ah*Bh + Ah*Bl + Al*Bh  (lo*lo dropped; ~fp32 accuracy)
// ===========================================================================
#define QW 20                 // 16 data u32 + 4 pad: frag LDS + STS conflict-free
// static smem: 4 tiles x 128 x QW u32 = 40960 B

__global__ __launch_bounds__(256, 2) void qkv_mma_kernel(
    const float* __restrict__ bq, const float* __restrict__ bk,
    const float* __restrict__ bv,
    float* __restrict__ kout, float* __restrict__ vout)
{
    __shared__ uint32_t sAh[128 * QW];
    __shared__ uint32_t sAl[128 * QW];
    __shared__ uint32_t sBh[128 * QW];
    __shared__ uint32_t sBl[128 * QW];

    const int tid = threadIdx.x, lane = tid & 31, warp = tid >> 5;
    const int gid = lane >> 2, tig = lane & 3;
    const int nt = blockIdx.x, mt = blockIdx.y, sel = blockIdx.z;

    const float* bias = (sel == 0) ? bq : (sel == 1) ? bk : bv;
    float* dst        = (sel == 0) ? g_q : (sel == 1) ? kout : vout;

    const int m0 = mt * 128, n0 = nt * 128;
    const int wm = (warp >> 2) * 64, wn = (warp & 3) * 32;

    // copy role: threads 0..127 -> A rows, 128..255 -> B rows
    const int part = tid >> 7;          // 0 = A, 1 = B
    const int cr   = tid & 127;         // row within tile
    const uint32_t* gh = part ? (g_Wh + (size_t)sel * (768 * 384) + (size_t)(n0 + cr) * 384)
                              : (g_Ah + (size_t)(m0 + cr) * 384);
    const uint32_t* gl = part ? (g_Wl + (size_t)sel * (768 * 384) + (size_t)(n0 + cr) * 384)
                              : (g_Al + (size_t)(m0 + cr) * 384);
    uint32_t* sh = part ? sBh : sAh;
    uint32_t* sl = part ? sBl : sAl;

    float acc[4][4][4];
#pragma unroll
    for (int mi = 0; mi < 4; mi++)
#pragma unroll
        for (int ni = 0; ni < 4; ni++)
#pragma unroll
            for (int j = 0; j < 4; j++) acc[mi][ni][j] = 0.f;

    for (int i = 0; i < 24; i++) {
        const int kp0 = i * 16;   // pair offset for this BK=32 chunk
        __syncthreads();
        {
            uint4 h[4], l[4];
#pragma unroll
            for (int p = 0; p < 4; p++) h[p] = ((const uint4*)(gh + kp0))[p];
#pragma unroll
            for (int p = 0; p < 4; p++) l[p] = ((const uint4*)(gl + kp0))[p];
#pragma unroll
            for (int p = 0; p < 4; p++) *(uint4*)&sh[cr * QW + p * 4] = h[p];
#pragma unroll
            for (int p = 0; p < 4; p++) *(uint4*)&sl[cr * QW + p * 4] = l[p];
        }
        __syncthreads();

#pragma unroll
        for (int kg = 0; kg < 2; kg++) {
            const int c0 = kg * 8 + tig;
            uint32_t ah[4][4], al[4][4];
#pragma unroll
            for (int mi = 0; mi < 4; mi++) {
                int r = wm + mi * 16 + gid;
                ah[mi][0] = sAh[r * QW + c0];
                ah[mi][1] = sAh[(r + 8) * QW + c0];
                ah[mi][2] = sAh[r * QW + c0 + 4];
                ah[mi][3] = sAh[(r + 8) * QW + c0 + 4];
                al[mi][0] = sAl[r * QW + c0];
                al[mi][1] = sAl[(r + 8) * QW + c0];
                al[mi][2] = sAl[r * QW + c0 + 4];
                al[mi][3] = sAl[(r + 8) * QW + c0 + 4];
            }
#pragma unroll
            for (int ni = 0; ni < 4; ni++) {
                int rn = wn + ni * 8 + gid;
                uint32_t bh[2], bl[2];
                bh[0] = sBh[rn * QW + c0];
                bh[1] = sBh[rn * QW + c0 + 4];
                bl[0] = sBl[rn * QW + c0];
                bl[1] = sBl[rn * QW + c0 + 4];
#pragma unroll
                for (int mi = 0; mi < 4; mi++) {
                    mma16(acc[mi][ni], ah[mi], bh);
                    mma16(acc[mi][ni], ah[mi], bl);
                    mma16(acc[mi][ni], al[mi], bh);
                }
            }
        }
    }

    // epilogue: bias + store into [B, nh, S, hd]
#pragma unroll
    for (int ni = 0; ni < 4; ni++) {
        int gn = n0 + wn + ni * 8 + 2 * tig;
        float b0 = __ldg(bias + gn), b1 = __ldg(bias + gn + 1);
        int hh = gn >> 6, dd = gn & 63;
#pragma unroll
        for (int mi = 0; mi < 4; mi++) {
            int gm = m0 + wm + mi * 16 + gid;
            int bb = gm >> 6, ss = gm & 63;
            float2 v0 = { acc[mi][ni][0] + b0, acc[mi][ni][1] + b1 };
            *(float2*)(dst + (((size_t)bb * NH_ + hh) * S_ + ss) * HD_ + dd) = v0;
            int gm2 = gm + 8;
            bb = gm2 >> 6; ss = gm2 & 63;
            float2 v1 = { acc[mi][ni][2] + b0, acc[mi][ni][3] + b1 };
            *(float2*)(dst + (((size_t)bb * NH_ + hh) * S_ + ss) * HD_ + dd) = v1;
        }
    }
}

// ===========================================================================
// Kernel 2: attention via tf32 mma.sync + online softmax (R3 version, control).
// ===========================================================================
#define KPAD 72

__global__ __launch_bounds__(128) void attn_mma_kernel(
    const float* __restrict__ kout, const float* __restrict__ vout,
    const float* __restrict__ c0k,  const float* __restrict__ c0v,
    const float* __restrict__ c1k,  const float* __restrict__ c1v,
    const float* __restrict__ mask, float* __restrict__ out)
{
    __shared__ uint32_t qs[64 * KPAD];
    __shared__ uint32_t ks[32 * KPAD];
    __shared__ uint32_t vs[32 * KPAD];
    __shared__ float msm[32];

    const unsigned FULL = 0xffffffffu;
    const int bh = blockIdx.x, b = bh / NH_, h = bh % NH_;
    const int tid = threadIdx.x, lane = tid & 31, warp = tid >> 5;
    const int gid = lane >> 2, tig = lane & 3;

    {
        const float* qp = g_q + (size_t)bh * S_ * HD_;
#pragma unroll
        for (int i = 0; i < 8; i++) {
            int idx = i * 128 + tid;
            int r = idx >> 4, c = (idx & 15) * 4;
            float4 v = *(const float4*)(qp + r * HD_ + c);
            uint32_t* p = &qs[r * KPAD + c];
            p[0] = f2tf(v.x * 0.125f); p[1] = f2tf(v.y * 0.125f);
            p[2] = f2tf(v.z * 0.125f); p[3] = f2tf(v.w * 0.125f);
        }
    }
    __syncthreads();

    uint32_t qf[8][4];
    {
        const int r = warp * 16 + gid;
#pragma unroll
        for (int kk = 0; kk < 8; kk++) {
            int c = kk * 8 + tig;
            qf[kk][0] = qs[r * KPAD + c];
            qf[kk][1] = qs[(r + 8) * KPAD + c];
            qf[kk][2] = qs[r * KPAD + c + 4];
            qf[kk][3] = qs[(r + 8) * KPAD + c + 4];
        }
    }

    float o[8][4];
#pragma unroll
    for (int nd = 0; nd < 8; nd++)
#pragma unroll
        for (int j = 0; j < 4; j++) o[nd][j] = 0.f;
    float m0 = -1e30f, m1 = -1e30f, l0 = 0.f, l1 = 0.f;

    const float* maskb = mask + (size_t)b * LT_;

    for (int seg = 0; seg < 3; seg++) {
        const float *kb, *vb;
        int len, posbase;
        if (seg == 0) {
            size_t off = ((size_t)(b % BS_) * NH_ + h) * L0_ * HD_;
            kb = c0k + off; vb = c0v + off; len = L0_; posbase = 0;
        } else if (seg == 1) {
            size_t off = ((size_t)b * NH_ + h) * L1_ * HD_;
            kb = c1k + off; vb = c1v + off; len = L1_; posbase = L0_;
        } else {
            size_t off = ((size_t)b * NH_ + h) * S_ * HD_;
            kb = kout + off; vb = vout + off; len = S_; posbase = L0_ + L1_;
        }

        for (int t = 0; t < len; t += 32) {
            __syncthreads();
#pragma unroll
            for (int i = 0; i < 4; i++) {
                int idx = i * 128 + tid;
                int r = idx >> 4, c = (idx & 15) * 4;
                float4 kv = *(const float4*)(kb + (size_t)(t + r) * HD_ + c);
                uint32_t* pk = &ks[r * KPAD + c];
                pk[0] = f2tf(kv.x); pk[1] = f2tf(kv.y); pk[2] = f2tf(kv.z); pk[3] = f2tf(kv.w);
                float4 vv = *(const float4*)(vb + (size_t)(t + r) * HD_ + c);
                uint32_t* pv = &vs[r * KPAD + c];
                pv[0] = f2tf(vv.x); pv[1] = f2tf(vv.y); pv[2] = f2tf(vv.z); pv[3] = f2tf(vv.w);
            }
            if (tid < 32) msm[tid] = maskb[posbase + t + tid];
            __syncthreads();

            float sc[4][4];
#pragma unroll
            for (int nb = 0; nb < 4; nb++) {
                sc[nb][0] = sc[nb][1] = sc[nb][2] = sc[nb][3] = 0.f;
#pragma unroll
                for (int kk = 0; kk < 8; kk++) {
                    uint32_t bf[2];
                    int rn = nb * 8 + gid, c = kk * 8 + tig;
                    bf[0] = ks[rn * KPAD + c];
                    bf[1] = ks[rn * KPAD + c + 4];
                    mma8(sc[nb], qf[kk], bf);
                }
                float mk0 = msm[nb * 8 + 2 * tig], mk1 = msm[nb * 8 + 2 * tig + 1];
                sc[nb][0] += mk0; sc[nb][1] += mk1;
                sc[nb][2] += mk0; sc[nb][3] += mk1;
            }

            float tm0 = -1e30f, tm1 = -1e30f;
#pragma unroll
            for (int nb = 0; nb < 4; nb++) {
                tm0 = fmaxf(tm0, fmaxf(sc[nb][0], sc[nb][1]));
                tm1 = fmaxf(tm1, fmaxf(sc[nb][2], sc[nb][3]));
            }
            tm0 = fmaxf(tm0, __shfl_xor_sync(FULL, tm0, 1));
            tm0 = fmaxf(tm0, __shfl_xor_sync(FULL, tm0, 2));
            tm1 = fmaxf(tm1, __shfl_xor_sync(FULL, tm1, 1));
            tm1 = fmaxf(tm1, __shfl_xor_sync(FULL, tm1, 2));
            float nm0 = fmaxf(m0, tm0), nm1 = fmaxf(m1, tm1);
            float cr0 = __expf(m0 - nm0), cr1 = __expf(m1 - nm1);
            m0 = nm0; m1 = nm1;
            l0 *= cr0; l1 *= cr1;

            uint32_t pt[4][4];
#pragma unroll
            for (int nb = 0; nb < 4; nb++) {
                float p0 = __expf(sc[nb][0] - m0), p1 = __expf(sc[nb][1] - m0);
                float p2 = __expf(sc[nb][2] - m1), p3 = __expf(sc[nb][3] - m1);
                l0 += p0 + p1; l1 += p2 + p3;
                pt[nb][0] = f2tf(p0); pt[nb][1] = f2tf(p1);
                pt[nb][2] = f2tf(p2); pt[nb][3] = f2tf(p3);
            }
#pragma unroll
            for (int nd = 0; nd < 8; nd++) {
                o[nd][0] *= cr0; o[nd][1] *= cr0;
                o[nd][2] *= cr1; o[nd][3] *= cr1;
            }

            const int srcA = (lane & ~3) | (tig >> 1);
            const int srcB = srcA + 2;
            const bool pk = tig & 1;
#pragma unroll
            for (int kc = 0; kc < 4; kc++) {
                uint32_t t0 = __shfl_sync(FULL, pt[kc][0], srcA);
                uint32_t t1 = __shfl_sync(FULL, pt[kc][1], srcA);
                uint32_t t2 = __shfl_sync(FULL, pt[kc][2], srcA);
                uint32_t t3 = __shfl_sync(FULL, pt[kc][3], srcA);
                uint32_t u0 = __shfl_sync(FULL, pt[kc][0], srcB);
                uint32_t u1 = __shfl_sync(FULL, pt[kc][1], srcB);
                uint32_t u2 = __shfl_sync(FULL, pt[kc][2], srcB);
                uint32_t u3 = __shfl_sync(FULL, pt[kc][3], srcB);
                uint32_t pa[4] = { pk ? t1 : t0, pk ? t3 : t2,
                                   pk ? u1 : u0, pk ? u3 : u2 };
#pragma unroll
                for (int nd = 0; nd < 8; nd++) {
                    uint32_t vf[2];
                    int rk = kc * 8 + tig, cn = nd * 8 + gid;
                    vf[0] = vs[rk * KPAD + cn];
                    vf[1] = vs[(rk + 4) * KPAD + cn];
                    mma8(o[nd], pa, vf);
                }
            }
        }
    }

    l0 += __shfl_xor_sync(FULL, l0, 1);
    l0 += __shfl_xor_sync(FULL, l0, 2);
    l1 += __shfl_xor_sync(FULL, l1, 1);
    l1 += __shfl_xor_sync(FULL, l1, 2);
    float i0 = 1.f / l0, i1 = 1.f / l1;

    const int s = warp * 16 + gid;
    float* ob  = out + ((size_t)b * S_ + s) * H_ + h * HD_;
    float* ob2 = out + ((size_t)b * S_ + s + 8) * H_ + h * HD_;
#pragma unroll
    for (int nd = 0; nd < 8; nd++) {
        int d = nd * 8 + 2 * tig;
        float2 v0 = { o[nd][0] * i0, o[nd][1] * i0 };
        float2 v1 = { o[nd][2] * i1, o[nd][3] * i1 };
        *(float2*)(ob + d)  = v0;
        *(float2*)(ob2 + d) = v1;
    }
}

// ---------------------------------------------------------------------------
extern "C" void kernel_launch(void* const* d_in, const int* in_sizes, int n_in,
                              void* d_out, int out_size)
{
    const float* hidden = (const float*)d_in[0];
    const float* mask   = (const float*)d_in[1];
    const float* Wq     = (const float*)d_in[2];
    const float* bq     = (const float*)d_in[3];
    const float* Wk     = (const float*)d_in[4];
    const float* bk     = (const float*)d_in[5];
    const float* Wv     = (const float*)d_in[6];
    const float* bv     = (const float*)d_in[7];
    const float* c0k    = (const float*)d_in[8];
    const float* c0v    = (const float*)d_in[9];
    const float* c1k    = (const float*)d_in[10];
    const float* c1v    = (const float*)d_in[11];

    float* out  = (float*)d_out;
    float* kout = out + (size_t)OUTSZ;
    float* vout = out + (size_t)2 * OUTSZ;

    prepack_kernel<<<(NF4_TOT + 255) / 256, 256>>>(hidden, Wq, Wk, Wv);

    dim3 g1(6, 120, 3);
    qkv_mma_kernel<<<g1, 256>>>(bq, bk, bv, kout, vout);

    attn_mma_kernel<<<B_ * NH_, 128>>>(kout, vout, c0k, c0v, c1k, c1v, mask, out);
}

// round 7
// speedup vs baseline: 1.3892x; 1.3892x over previous
#include <cuda_runtime.h>
#include <cuda_fp16.h>
#include <cstdint>

// Problem constants (fixed shapes)
#define B_    240
#define S_    64
#define H_    768
#define NH_   12
#define HD_   64
#define L0_   384
#define L1_   128
#define LT_   576          // L0+L1+S
#define BS_   8            // cache0 batch = 240/30
#define OUTSZ (B_*S_*H_)   // 11796480

// scratch for q in [B, nh, S, hd] layout (fp32)
__device__ float g_q[B_ * NH_ * S_ * HD_];

// ---------------------------------------------------------------------------
// helpers
// ---------------------------------------------------------------------------
__device__ __forceinline__ uint32_t packh2(float lo, float hi) {
    __half2 h = __floats2half2_rn(lo, hi);     // .x = lo (low 16 bits)
    return *reinterpret_cast<uint32_t*>(&h);
}

// D(16x8,f32) += A(16x16,f16) * B(16x8,f16)
__device__ __forceinline__ void mma16(float* d, const uint32_t* a, const uint32_t* b) {
    asm volatile(
        "mma.sync.aligned.m16n8k16.row.col.f32.f16.f16.f32 "
        "{%0,%1,%2,%3}, {%4,%5,%6,%7}, {%8,%9}, {%0,%1,%2,%3};"
        : "+f"(d[0]), "+f"(d[1]), "+f"(d[2]), "+f"(d[3])
        : "r"(a[0]), "r"(a[1]), "r"(a[2]), "r"(a[3]), "r"(b[0]), "r"(b[1]));
}

// ===========================================================================
// Kernel 1: QKV projection via fp16 m16n8k16 mma.sync.
// C[15360,768] = hidden @ W^T + bias -> [B, nh, S, hd] layout.
// 128x128 CTA tile, BK=32 floats (2 k16 groups), 256 thr (8 warps, 64x32).
// fp32 -> packed fp16x2 at smem staging (one cvt per element).
// ===========================================================================
#define QW 20   // 16 data u32 (32 halves) + 4 pad: conflict-free frag LDS

__global__ __launch_bounds__(256, 2) void qkv_mma_kernel(
    const float* __restrict__ hidden,
    const float* __restrict__ Wq, const float* __restrict__ bq,
    const float* __restrict__ Wk, const float* __restrict__ bk,
    const float* __restrict__ Wv, const float* __restrict__ bv,
    float* __restrict__ kout, float* __restrict__ vout)
{
    __shared__ uint32_t sA[128 * QW];
    __shared__ uint32_t sB[128 * QW];

    const int tid = threadIdx.x, lane = tid & 31, warp = tid >> 5;
    const int gid = lane >> 2, tig = lane & 3;
    const int nt = blockIdx.x, mt = blockIdx.y, sel = blockIdx.z;

    const float* W    = (sel == 0) ? Wq : (sel == 1) ? Wk : Wv;
    const float* bias = (sel == 0) ? bq : (sel == 1) ? bk : bv;
    float* dst        = (sel == 0) ? g_q : (sel == 1) ? kout : vout;

    const int m0 = mt * 128, n0 = nt * 128;
    const int wm = (warp >> 2) * 64, wn = (warp & 3) * 32;

    // copy role: threads 0..127 -> one A row each; 128..255 -> one B row
    const int part = tid >> 7;
    const int cr   = tid & 127;
    const float* grow = part ? (W + (size_t)(n0 + cr) * H_)
                             : (hidden + (size_t)(m0 + cr) * H_);
    uint32_t* srow = (part ? sB : sA) + cr * QW;

    float acc[4][4][4];
#pragma unroll
    for (int mi = 0; mi < 4; mi++)
#pragma unroll
        for (int ni = 0; ni < 4; ni++)
#pragma unroll
            for (int j = 0; j < 4; j++) acc[mi][ni][j] = 0.f;

    for (int i = 0; i < 24; i++) {
        const int k0 = i * 32;
        __syncthreads();
        {
            float4 v[8];
#pragma unroll
            for (int p = 0; p < 8; p++)
                v[p] = *(const float4*)(grow + k0 + p * 4);
#pragma unroll
            for (int p = 0; p < 4; p++) {
                uint4 t;
                t.x = packh2(v[2*p].x,   v[2*p].y);
                t.y = packh2(v[2*p].z,   v[2*p].w);
                t.z = packh2(v[2*p+1].x, v[2*p+1].y);
                t.w = packh2(v[2*p+1].z, v[2*p+1].w);
                *(uint4*)&srow[p * 4] = t;
            }
        }
        __syncthreads();

#pragma unroll
        for (int kg = 0; kg < 2; kg++) {
            const int c0 = kg * 8 + tig;
            uint32_t a[4][4], bf[4][2];
#pragma unroll
            for (int mi = 0; mi < 4; mi++) {
                int r = wm + mi * 16 + gid;
                a[mi][0] = sA[r * QW + c0];
                a[mi][1] = sA[(r + 8) * QW + c0];
                a[mi][2] = sA[r * QW + c0 + 4];
                a[mi][3] = sA[(r + 8) * QW + c0 + 4];
            }
#pragma unroll
            for (int ni = 0; ni < 4; ni++) {
                int rn = wn + ni * 8 + gid;
                bf[ni][0] = sB[rn * QW + c0];
                bf[ni][1] = sB[rn * QW + c0 + 4];
            }
#pragma unroll
            for (int mi = 0; mi < 4; mi++)
#pragma unroll
                for (int ni = 0; ni < 4; ni++)
                    mma16(acc[mi][ni], a[mi], bf[ni]);
        }
    }

    // epilogue: bias + store into [B, nh, S, hd]
#pragma unroll
    for (int ni = 0; ni < 4; ni++) {
        int gn = n0 + wn + ni * 8 + 2 * tig;
        float b0 = __ldg(bias + gn), b1 = __ldg(bias + gn + 1);
        int hh = gn >> 6, dd = gn & 63;
#pragma unroll
        for (int mi = 0; mi < 4; mi++) {
            int gm = m0 + wm + mi * 16 + gid;
            int bb = gm >> 6, ss = gm & 63;
            float2 v0 = { acc[mi][ni][0] + b0, acc[mi][ni][1] + b1 };
            *(float2*)(dst + (((size_t)bb * NH_ + hh) * S_ + ss) * HD_ + dd) = v0;
            int gm2 = gm + 8;
            bb = gm2 >> 6; ss = gm2 & 63;
            float2 v1 = { acc[mi][ni][2] + b0, acc[mi][ni][3] + b1 };
            *(float2*)(dst + (((size_t)bb * NH_ + hh) * S_ + ss) * HD_ + dd) = v1;
        }
    }
}

// ===========================================================================
// Kernel 2: attention via fp16 m16n8k16 mma.sync + online softmax.
// One block per (b,h), 4 warps x 16 q-rows, 32-key tiles.
// P: C-layout == k16 A-layout under half2 packing -> NO shuffles.
// V staged transposed (vsT[dim][key-pair]) for the PV B-fragments.
// ===========================================================================
#define KW 36   // 32 data u32 + 4 pad (qs, ks rows)
#define VW 20   // 16 data u32 + 4 pad (vsT rows)

__global__ __launch_bounds__(128) void attn_mma_kernel(
    const float* __restrict__ kout, const float* __restrict__ vout,
    const float* __restrict__ c0k,  const float* __restrict__ c0v,
    const float* __restrict__ c1k,  const float* __restrict__ c1v,
    const float* __restrict__ mask, float* __restrict__ out)
{
    __shared__ uint32_t qs[64 * KW];     // Q: 64 rows x 64 halves
    __shared__ uint32_t ks[32 * KW];     // K: 32 keys x 64 halves
    __shared__ uint32_t vsT[64 * VW];    // V^T: 64 dims x 32 halves (keys)
    __shared__ float msm[32];

    const unsigned FULL = 0xffffffffu;
    const int bh = blockIdx.x, b = bh / NH_, h = bh % NH_;
    const int tid = threadIdx.x, lane = tid & 31, warp = tid >> 5;
    const int gid = lane >> 2, tig = lane & 3;

    // stage Q (pre-scaled by 1/8) as packed fp16
    {
        const float* qp = g_q + (size_t)bh * S_ * HD_;
#pragma unroll
        for (int p = 0; p < 8; p++) {
            int idx = p * 128 + tid;
            int r = idx >> 4, c4 = idx & 15;
            float4 v = *(const float4*)(qp + r * HD_ + c4 * 4);
            uint2 t = { packh2(v.x * 0.125f, v.y * 0.125f),
                        packh2(v.z * 0.125f, v.w * 0.125f) };
            *(uint2*)&qs[r * KW + c4 * 2] = t;
        }
    }
    __syncthreads();

    // Q fragments: qf[kk] covers k-dims 16*kk .. 16*kk+15
    uint32_t qf[4][4];
    {
        const int r = warp * 16 + gid;
#pragma unroll
        for (int kk = 0; kk < 4; kk++) {
            int c = kk * 8 + tig;
            qf[kk][0] = qs[r * KW + c];
            qf[kk][1] = qs[(r + 8) * KW + c];
            qf[kk][2] = qs[r * KW + c + 4];
            qf[kk][3] = qs[(r + 8) * KW + c + 4];
        }
    }

    float o[8][4];
#pragma unroll
    for (int nd = 0; nd < 8; nd++)
#pragma unroll
        for (int j = 0; j < 4; j++) o[nd][j] = 0.f;
    float m0 = -1e30f, m1 = -1e30f, l0 = 0.f, l1 = 0.f;

    const float* maskb = mask + (size_t)b * LT_;
    const int kp = tid & 15, dg = tid >> 4;   // V-transpose staging coords

    for (int seg = 0; seg < 3; seg++) {
        const float *kb, *vb;
        int len, posbase;
        if (seg == 0) {
            size_t off = ((size_t)(b % BS_) * NH_ + h) * L0_ * HD_;
            kb = c0k + off; vb = c0v + off; len = L0_; posbase = 0;
        } else if (seg == 1) {
            size_t off = ((size_t)b * NH_ + h) * L1_ * HD_;
            kb = c1k + off; vb = c1v + off; len = L1_; posbase = L0_;
        } else {
            size_t off = ((size_t)b * NH_ + h) * S_ * HD_;
            kb = kout + off; vb = vout + off; len = S_; posbase = L0_ + L1_;
        }

        for (int t = 0; t < len; t += 32) {
            __syncthreads();
            // K: rows = keys, packed along d
#pragma unroll
            for (int p = 0; p < 4; p++) {
                int idx = p * 128 + tid;
                int r = idx >> 4, c4 = idx & 15;
                float4 kv = *(const float4*)(kb + (size_t)(t + r) * HD_ + c4 * 4);
                uint2 tk = { packh2(kv.x, kv.y), packh2(kv.z, kv.w) };
                *(uint2*)&ks[r * KW + c4 * 2] = tk;
            }
            // V transposed: vsT[d][kp] = h2(V[2kp][d], V[2kp+1][d])
            {
                const float* v0 = vb + (size_t)(t + 2 * kp) * HD_ + dg * 8;
                const float* v1 = v0 + HD_;
                float4 a0 = *(const float4*)(v0);
                float4 a1 = *(const float4*)(v0 + 4);
                float4 b0 = *(const float4*)(v1);
                float4 b1 = *(const float4*)(v1 + 4);
                int dbase = dg * 8;
                vsT[(dbase + 0) * VW + kp] = packh2(a0.x, b0.x);
                vsT[(dbase + 1) * VW + kp] = packh2(a0.y, b0.y);
                vsT[(dbase + 2) * VW + kp] = packh2(a0.z, b0.z);
                vsT[(dbase + 3) * VW + kp] = packh2(a0.w, b0.w);
                vsT[(dbase + 4) * VW + kp] = packh2(a1.x, b1.x);
                vsT[(dbase + 5) * VW + kp] = packh2(a1.y, b1.y);
                vsT[(dbase + 6) * VW + kp] = packh2(a1.z, b1.z);
                vsT[(dbase + 7) * VW + kp] = packh2(a1.w, b1.w);
            }
            if (tid < 32) msm[tid] = maskb[posbase + t + tid];
            __syncthreads();

            // scores: S[16 rows][32 keys] per warp (4 n-blocks x 4 k16 groups)
            float sc[4][4];
#pragma unroll
            for (int nb = 0; nb < 4; nb++) {
                sc[nb][0] = sc[nb][1] = sc[nb][2] = sc[nb][3] = 0.f;
#pragma unroll
                for (int kk = 0; kk < 4; kk++) {
                    uint32_t bf[2];
                    int rn = nb * 8 + gid, c = kk * 8 + tig;
                    bf[0] = ks[rn * KW + c];
                    bf[1] = ks[rn * KW + c + 4];
                    mma16(sc[nb], qf[kk], bf);
                }
                float mk0 = msm[nb * 8 + 2 * tig], mk1 = msm[nb * 8 + 2 * tig + 1];
                sc[nb][0] += mk0; sc[nb][1] += mk1;
                sc[nb][2] += mk0; sc[nb][3] += mk1;
            }

            // online softmax (rows r = gid and r+8)
            float tm0 = -1e30f, tm1 = -1e30f;
#pragma unroll
            for (int nb = 0; nb < 4; nb++) {
                tm0 = fmaxf(tm0, fmaxf(sc[nb][0], sc[nb][1]));
                tm1 = fmaxf(tm1, fmaxf(sc[nb][2], sc[nb][3]));
            }
            tm0 = fmaxf(tm0, __shfl_xor_sync(FULL, tm0, 1));
            tm0 = fmaxf(tm0, __shfl_xor_sync(FULL, tm0, 2));
            tm1 = fmaxf(tm1, __shfl_xor_sync(FULL, tm1, 1));
            tm1 = fmaxf(tm1, __shfl_xor_sync(FULL, tm1, 2));
            float nm0 = fmaxf(m0, tm0), nm1 = fmaxf(m1, tm1);
            float cr0 = __expf(m0 - nm0), cr1 = __expf(m1 - nm1);
            m0 = nm0; m1 = nm1;
            l0 *= cr0; l1 *= cr1;

            // exp + pack P directly into k16 A-fragments (no shuffles!)
            uint32_t pa[2][4];
#pragma unroll
            for (int kc = 0; kc < 2; kc++) {
                float p00 = __expf(sc[2*kc][0]   - m0), p01 = __expf(sc[2*kc][1]   - m0);
                float p02 = __expf(sc[2*kc][2]   - m1), p03 = __expf(sc[2*kc][3]   - m1);
                float p10 = __expf(sc[2*kc+1][0] - m0), p11 = __expf(sc[2*kc+1][1] - m0);
                float p12 = __expf(sc[2*kc+1][2] - m1), p13 = __expf(sc[2*kc+1][3] - m1);
                l0 += p00 + p01 + p10 + p11;
                l1 += p02 + p03 + p12 + p13;
                pa[kc][0] = packh2(p00, p01);   // row gid,  keys 16kc+2tig..+1
                pa[kc][1] = packh2(p02, p03);   // row gid+8, same keys
                pa[kc][2] = packh2(p10, p11);   // row gid,  keys 16kc+8+2tig
                pa[kc][3] = packh2(p12, p13);   // row gid+8
            }
#pragma unroll
            for (int nd = 0; nd < 8; nd++) {
                o[nd][0] *= cr0; o[nd][1] *= cr0;
                o[nd][2] *= cr1; o[nd][3] *= cr1;
            }

            // P @ V : 2 k16 groups x 8 dim-blocks
#pragma unroll
            for (int kc = 0; kc < 2; kc++) {
#pragma unroll
                for (int nd = 0; nd < 8; nd++) {
                    uint32_t vf[2];
                    int rd = nd * 8 + gid, c = kc * 8 + tig;
                    vf[0] = vsT[rd * VW + c];
                    vf[1] = vsT[rd * VW + c + 4];
                    mma16(o[nd], pa[kc], vf);
                }
            }
        }
    }

    l0 += __shfl_xor_sync(FULL, l0, 1);
    l0 += __shfl_xor_sync(FULL, l0, 2);
    l1 += __shfl_xor_sync(FULL, l1, 1);
    l1 += __shfl_xor_sync(FULL, l1, 2);
    float i0 = 1.f / l0, i1 = 1.f / l1;

    const int s = warp * 16 + gid;
    float* ob  = out + ((size_t)b * S_ + s) * H_ + h * HD_;
    float* ob2 = out + ((size_t)b * S_ + s + 8) * H_ + h * HD_;
#pragma unroll
    for (int nd = 0; nd < 8; nd++) {
        int d = nd * 8 + 2 * tig;
        float2 v0 = { o[nd][0] * i0, o[nd][1] * i0 };
        float2 v1 = { o[nd][2] * i1, o[nd][3] * i1 };
        *(float2*)(ob + d)  = v0;
        *(float2*)(ob2 + d) = v1;
    }
}

// ---------------------------------------------------------------------------
extern "C" void kernel_launch(void* const* d_in, const int* in_sizes, int n_in,
                              void* d_out, int out_size)
{
    const float* hidden = (const float*)d_in[0];
    const float* mask   = (const float*)d_in[1];
    const float* Wq     = (const float*)d_in[2];
    const float* bq     = (const float*)d_in[3];
    const float* Wk     = (const float*)d_in[4];
    const float* bk     = (const float*)d_in[5];
    const float* Wv     = (const float*)d_in[6];
    const float* bv     = (const float*)d_in[7];
    const float* c0k    = (const float*)d_in[8];
    const float* c0v    = (const float*)d_in[9];
    const float* c1k    = (const float*)d_in[10];
    const float* c1v    = (const float*)d_in[11];

    float* out  = (float*)d_out;
    float* kout = out + (size_t)OUTSZ;
    float* vout = out + (size_t)2 * OUTSZ;

    dim3 g1(6, 120, 3);
    qkv_mma_kernel<<<g1, 256>>>(hidden, Wq, bq, Wk, bk, Wv, bv, kout, vout);

    attn_mma_kernel<<<B_ * NH_, 128>>>(kout, vout, c0k, c0v, c1k, c1v, mask, out);
}

// round 8
// speedup vs baseline: 2.0661x; 1.4872x over previous
#include <cuda_runtime.h>
#include <cuda_fp16.h>
#include <cstdint>

// Problem constants (fixed shapes)
#define B_    240
#define S_    64
#define H_    768
#define NH_   12
#define HD_   64
#define L0_   384
#define L1_   128
#define LT_   576          // L0+L1+S
#define BS_   8            // cache0 batch = 240/30
#define OUTSZ (B_*S_*H_)   // 11796480

// scratch for q in [B, nh, S, hd] layout (fp32)
__device__ float g_q[B_ * NH_ * S_ * HD_];

// ---------------------------------------------------------------------------
// helpers
// ---------------------------------------------------------------------------
__device__ __forceinline__ uint32_t packh2(float lo, float hi) {
    __half2 h = __floats2half2_rn(lo, hi);     // .x = lo (low 16 bits)
    return *reinterpret_cast<uint32_t*>(&h);
}

// D(16x8,f32) += A(16x16,f16) * B(16x8,f16)
__device__ __forceinline__ void mma16(float* d, const uint32_t* a, const uint32_t* b) {
    asm volatile(
        "mma.sync.aligned.m16n8k16.row.col.f32.f16.f16.f32 "
        "{%0,%1,%2,%3}, {%4,%5,%6,%7}, {%8,%9}, {%0,%1,%2,%3};"
        : "+f"(d[0]), "+f"(d[1]), "+f"(d[2]), "+f"(d[3])
        : "r"(a[0]), "r"(a[1]), "r"(a[2]), "r"(a[3]), "r"(b[0]), "r"(b[1]));
}

// ===========================================================================
// Kernel 1: QKV projection via fp16 m16n8k16 mma.sync.
// C[15360,768] = hidden @ W^T + bias -> [B, nh, S, hd] layout.
// 128x128 CTA tile, BK=64 floats (4 k16 groups), 256 thr (8 warps, 64x32).
// Coalesced staging: 8 threads cover one row's 256B; LDG.128 = 2 lines.
// ===========================================================================
#define QW 36   // 32 data u32 (64 halves) + 4 pad: frag LDS conflict-free

__global__ __launch_bounds__(256, 2) void qkv_mma_kernel(
    const float* __restrict__ hidden,
    const float* __restrict__ Wq, const float* __restrict__ bq,
    const float* __restrict__ Wk, const float* __restrict__ bk,
    const float* __restrict__ Wv, const float* __restrict__ bv,
    float* __restrict__ kout, float* __restrict__ vout)
{
    __shared__ uint32_t sA[128 * QW];
    __shared__ uint32_t sB[128 * QW];

    const int tid = threadIdx.x, lane = tid & 31, warp = tid >> 5;
    const int gid = lane >> 2, tig = lane & 3;
    const int nt = blockIdx.x, mt = blockIdx.y, sel = blockIdx.z;

    const float* W    = (sel == 0) ? Wq : (sel == 1) ? Wk : Wv;
    const float* bias = (sel == 0) ? bq : (sel == 1) ? bk : bv;
    float* dst        = (sel == 0) ? g_q : (sel == 1) ? kout : vout;

    const int m0 = mt * 128, n0 = nt * 128;
    const int wm = (warp >> 2) * 64, wn = (warp & 3) * 32;

    float acc[4][4][4];
#pragma unroll
    for (int mi = 0; mi < 4; mi++)
#pragma unroll
        for (int ni = 0; ni < 4; ni++)
#pragma unroll
            for (int j = 0; j < 4; j++) acc[mi][ni][j] = 0.f;

    for (int i = 0; i < 12; i++) {
        const int k0 = i * 64;
        __syncthreads();
        // stage A then B: group g = p*256+tid -> row g>>3, 8 floats at (g&7)*8
        {
            float4 va[8];
#pragma unroll
            for (int p = 0; p < 4; p++) {
                int g = p * 256 + tid;
                const float* src = hidden + (size_t)(m0 + (g >> 3)) * H_ + k0 + (g & 7) * 8;
                va[2*p]   = *(const float4*)(src);
                va[2*p+1] = *(const float4*)(src + 4);
            }
#pragma unroll
            for (int p = 0; p < 4; p++) {
                int g = p * 256 + tid;
                uint4 t;
                t.x = packh2(va[2*p].x,   va[2*p].y);
                t.y = packh2(va[2*p].z,   va[2*p].w);
                t.z = packh2(va[2*p+1].x, va[2*p+1].y);
                t.w = packh2(va[2*p+1].z, va[2*p+1].w);
                *(uint4*)&sA[(g >> 3) * QW + (g & 7) * 4] = t;
            }
#pragma unroll
            for (int p = 0; p < 4; p++) {
                int g = p * 256 + tid;
                const float* src = W + (size_t)(n0 + (g >> 3)) * H_ + k0 + (g & 7) * 8;
                va[2*p]   = *(const float4*)(src);
                va[2*p+1] = *(const float4*)(src + 4);
            }
#pragma unroll
            for (int p = 0; p < 4; p++) {
                int g = p * 256 + tid;
                uint4 t;
                t.x = packh2(va[2*p].x,   va[2*p].y);
                t.y = packh2(va[2*p].z,   va[2*p].w);
                t.z = packh2(va[2*p+1].x, va[2*p+1].y);
                t.w = packh2(va[2*p+1].z, va[2*p+1].w);
                *(uint4*)&sB[(g >> 3) * QW + (g & 7) * 4] = t;
            }
        }
        __syncthreads();

#pragma unroll
        for (int kg = 0; kg < 4; kg++) {
            const int c0 = kg * 8 + tig;
            uint32_t a[4][4], bf[4][2];
#pragma unroll
            for (int mi = 0; mi < 4; mi++) {
                int r = wm + mi * 16 + gid;
                a[mi][0] = sA[r * QW + c0];
                a[mi][1] = sA[(r + 8) * QW + c0];
                a[mi][2] = sA[r * QW + c0 + 4];
                a[mi][3] = sA[(r + 8) * QW + c0 + 4];
            }
#pragma unroll
            for (int ni = 0; ni < 4; ni++) {
                int rn = wn + ni * 8 + gid;
                bf[ni][0] = sB[rn * QW + c0];
                bf[ni][1] = sB[rn * QW + c0 + 4];
            }
#pragma unroll
            for (int mi = 0; mi < 4; mi++)
#pragma unroll
                for (int ni = 0; ni < 4; ni++)
                    mma16(acc[mi][ni], a[mi], bf[ni]);
        }
    }

    // epilogue: bias + store into [B, nh, S, hd]
#pragma unroll
    for (int ni = 0; ni < 4; ni++) {
        int gn = n0 + wn + ni * 8 + 2 * tig;
        float b0 = __ldg(bias + gn), b1 = __ldg(bias + gn + 1);
        int hh = gn >> 6, dd = gn & 63;
#pragma unroll
        for (int mi = 0; mi < 4; mi++) {
            int gm = m0 + wm + mi * 16 + gid;
            int bb = gm >> 6, ss = gm & 63;
            float2 v0 = { acc[mi][ni][0] + b0, acc[mi][ni][1] + b1 };
            *(float2*)(dst + (((size_t)bb * NH_ + hh) * S_ + ss) * HD_ + dd) = v0;
            int gm2 = gm + 8;
            bb = gm2 >> 6; ss = gm2 & 63;
            float2 v1 = { acc[mi][ni][2] + b0, acc[mi][ni][3] + b1 };
            *(float2*)(dst + (((size_t)bb * NH_ + hh) * S_ + ss) * HD_ + dd) = v1;
        }
    }
}

// ===========================================================================
// Kernel 2: attention via fp16 m16n8k16 mma.sync + online softmax.
// (unchanged from R7 — the 237us control)
// ===========================================================================
#define KW 36   // 32 data u32 + 4 pad (qs, ks rows)
#define VW 20   // 16 data u32 + 4 pad (vsT rows)

__global__ __launch_bounds__(128) void attn_mma_kernel(
    const float* __restrict__ kout, const float* __restrict__ vout,
    const float* __restrict__ c0k,  const float* __restrict__ c0v,
    const float* __restrict__ c1k,  const float* __restrict__ c1v,
    const float* __restrict__ mask, float* __restrict__ out)
{
    __shared__ uint32_t qs[64 * KW];     // Q: 64 rows x 64 halves
    __shared__ uint32_t ks[32 * KW];     // K: 32 keys x 64 halves
    __shared__ uint32_t vsT[64 * VW];    // V^T: 64 dims x 32 halves (keys)
    __shared__ float msm[32];

    const unsigned FULL = 0xffffffffu;
    const int bh = blockIdx.x, b = bh / NH_, h = bh % NH_;
    const int tid = threadIdx.x, lane = tid & 31, warp = tid >> 5;
    const int gid = lane >> 2, tig = lane & 3;

    // stage Q (pre-scaled by 1/8) as packed fp16
    {
        const float* qp = g_q + (size_t)bh * S_ * HD_;
#pragma unroll
        for (int p = 0; p < 8; p++) {
            int idx = p * 128 + tid;
            int r = idx >> 4, c4 = idx & 15;
            float4 v = *(const float4*)(qp + r * HD_ + c4 * 4);
            uint2 t = { packh2(v.x * 0.125f, v.y * 0.125f),
                        packh2(v.z * 0.125f, v.w * 0.125f) };
            *(uint2*)&qs[r * KW + c4 * 2] = t;
        }
    }
    __syncthreads();

    // Q fragments: qf[kk] covers k-dims 16*kk .. 16*kk+15
    uint32_t qf[4][4];
    {
        const int r = warp * 16 + gid;
#pragma unroll
        for (int kk = 0; kk < 4; kk++) {
            int c = kk * 8 + tig;
            qf[kk][0] = qs[r * KW + c];
            qf[kk][1] = qs[(r + 8) * KW + c];
            qf[kk][2] = qs[r * KW + c + 4];
            qf[kk][3] = qs[(r + 8) * KW + c + 4];
        }
    }

    float o[8][4];
#pragma unroll
    for (int nd = 0; nd < 8; nd++)
#pragma unroll
        for (int j = 0; j < 4; j++) o[nd][j] = 0.f;
    float m0 = -1e30f, m1 = -1e30f, l0 = 0.f, l1 = 0.f;

    const float* maskb = mask + (size_t)b * LT_;
    const int kp = tid & 15, dg = tid >> 4;   // V-transpose staging coords

    for (int seg = 0; seg < 3; seg++) {
        const float *kb, *vb;
        int len, posbase;
        if (seg == 0) {
            size_t off = ((size_t)(b % BS_) * NH_ + h) * L0_ * HD_;
            kb = c0k + off; vb = c0v + off; len = L0_; posbase = 0;
        } else if (seg == 1) {
            size_t off = ((size_t)b * NH_ + h) * L1_ * HD_;
            kb = c1k + off; vb = c1v + off; len = L1_; posbase = L0_;
        } else {
            size_t off = ((size_t)b * NH_ + h) * S_ * HD_;
            kb = kout + off; vb = vout + off; len = S_; posbase = L0_ + L1_;
        }

        for (int t = 0; t < len; t += 32) {
            __syncthreads();
            // K: rows = keys, packed along d
#pragma unroll
            for (int p = 0; p < 4; p++) {
                int idx = p * 128 + tid;
                int r = idx >> 4, c4 = idx & 15;
                float4 kv = *(const float4*)(kb + (size_t)(t + r) * HD_ + c4 * 4);
                uint2 tk = { packh2(kv.x, kv.y), packh2(kv.z, kv.w) };
                *(uint2*)&ks[r * KW + c4 * 2] = tk;
            }
            // V transposed: vsT[d][kp] = h2(V[2kp][d], V[2kp+1][d])
            {
                const float* v0 = vb + (size_t)(t + 2 * kp) * HD_ + dg * 8;
                const float* v1 = v0 + HD_;
                float4 a0 = *(const float4*)(v0);
                float4 a1 = *(const float4*)(v0 + 4);
                float4 b0 = *(const float4*)(v1);
                float4 b1 = *(const float4*)(v1 + 4);
                int dbase = dg * 8;
                vsT[(dbase + 0) * VW + kp] = packh2(a0.x, b0.x);
                vsT[(dbase + 1) * VW + kp] = packh2(a0.y, b0.y);
                vsT[(dbase + 2) * VW + kp] = packh2(a0.z, b0.z);
                vsT[(dbase + 3) * VW + kp] = packh2(a0.w, b0.w);
                vsT[(dbase + 4) * VW + kp] = packh2(a1.x, b1.x);
                vsT[(dbase + 5) * VW + kp] = packh2(a1.y, b1.y);
                vsT[(dbase + 6) * VW + kp] = packh2(a1.z, b1.z);
                vsT[(dbase + 7) * VW + kp] = packh2(a1.w, b1.w);
            }
            if (tid < 32) msm[tid] = maskb[posbase + t + tid];
            __syncthreads();

            // scores: S[16 rows][32 keys] per warp (4 n-blocks x 4 k16 groups)
            float sc[4][4];
#pragma unroll
            for (int nb = 0; nb < 4; nb++) {
                sc[nb][0] = sc[nb][1] = sc[nb][2] = sc[nb][3] = 0.f;
#pragma unroll
                for (int kk = 0; kk < 4; kk++) {
                    uint32_t bf[2];
                    int rn = nb * 8 + gid, c = kk * 8 + tig;
                    bf[0] = ks[rn * KW + c];
                    bf[1] = ks[rn * KW + c + 4];
                    mma16(sc[nb], qf[kk], bf);
                }
                float mk0 = msm[nb * 8 + 2 * tig], mk1 = msm[nb * 8 + 2 * tig + 1];
                sc[nb][0] += mk0; sc[nb][1] += mk1;
                sc[nb][2] += mk0; sc[nb][3] += mk1;
            }

            // online softmax (rows r = gid and r+8)
            float tm0 = -1e30f, tm1 = -1e30f;
#pragma unroll
            for (int nb = 0; nb < 4; nb++) {
                tm0 = fmaxf(tm0, fmaxf(sc[nb][0], sc[nb][1]));
                tm1 = fmaxf(tm1, fmaxf(sc[nb][2], sc[nb][3]));
            }
            tm0 = fmaxf(tm0, __shfl_xor_sync(FULL, tm0, 1));
            tm0 = fmaxf(tm0, __shfl_xor_sync(FULL, tm0, 2));
            tm1 = fmaxf(tm1, __shfl_xor_sync(FULL, tm1, 1));
            tm1 = fmaxf(tm1, __shfl_xor_sync(FULL, tm1, 2));
            float nm0 = fmaxf(m0, tm0), nm1 = fmaxf(m1, tm1);
            float cr0 = __expf(m0 - nm0), cr1 = __expf(m1 - nm1);
            m0 = nm0; m1 = nm1;
            l0 *= cr0; l1 *= cr1;

            // exp + pack P directly into k16 A-fragments (no shuffles!)
            uint32_t pa[2][4];
#pragma unroll
            for (int kc = 0; kc < 2; kc++) {
                float p00 = __expf(sc[2*kc][0]   - m0), p01 = __expf(sc[2*kc][1]   - m0);
                float p02 = __expf(sc[2*kc][2]   - m1), p03 = __expf(sc[2*kc][3]   - m1);
                float p10 = __expf(sc[2*kc+1][0] - m0), p11 = __expf(sc[2*kc+1][1] - m0);
                float p12 = __expf(sc[2*kc+1][2] - m1), p13 = __expf(sc[2*kc+1][3] - m1);
                l0 += p00 + p01 + p10 + p11;
                l1 += p02 + p03 + p12 + p13;
                pa[kc][0] = packh2(p00, p01);
                pa[kc][1] = packh2(p02, p03);
                pa[kc][2] = packh2(p10, p11);
                pa[kc][3] = packh2(p12, p13);
            }
#pragma unroll
            for (int nd = 0; nd < 8; nd++) {
                o[nd][0] *= cr0; o[nd][1] *= cr0;
                o[nd][2] *= cr1; o[nd][3] *= cr1;
            }

            // P @ V : 2 k16 groups x 8 dim-blocks
#pragma unroll
            for (int kc = 0; kc < 2; kc++) {
#pragma unroll
                for (int nd = 0; nd < 8; nd++) {
                    uint32_t vf[2];
                    int rd = nd * 8 + gid, c = kc * 8 + tig;
                    vf[0] = vsT[rd * VW + c];
                    vf[1] = vsT[rd * VW + c + 4];
                    mma16(o[nd], pa[kc], vf);
                }
            }
        }
    }

    l0 += __shfl_xor_sync(FULL, l0, 1);
    l0 += __shfl_xor_sync(FULL, l0, 2);
    l1 += __shfl_xor_sync(FULL, l1, 1);
    l1 += __shfl_xor_sync(FULL, l1, 2);
    float i0 = 1.f / l0, i1 = 1.f / l1;

    const int s = warp * 16 + gid;
    float* ob  = out + ((size_t)b * S_ + s) * H_ + h * HD_;
    float* ob2 = out + ((size_t)b * S_ + s + 8) * H_ + h * HD_;
#pragma unroll
    for (int nd = 0; nd < 8; nd++) {
        int d = nd * 8 + 2 * tig;
        float2 v0 = { o[nd][0] * i0, o[nd][1] * i0 };
        float2 v1 = { o[nd][2] * i1, o[nd][3] * i1 };
        *(float2*)(ob + d)  = v0;
        *(float2*)(ob2 + d) = v1;
    }
}

// ---------------------------------------------------------------------------
extern "C" void kernel_launch(void* const* d_in, const int* in_sizes, int n_in,
                              void* d_out, int out_size)
{
    const float* hidden = (const float*)d_in[0];
    const float* mask   = (const float*)d_in[1];
    const float* Wq     = (const float*)d_in[2];
    const float* bq     = (const float*)d_in[3];
    const float* Wk     = (const float*)d_in[4];
    const float* bk     = (const float*)d_in[5];
    const float* Wv     = (const float*)d_in[6];
    const float* bv     = (const float*)d_in[7];
    const float* c0k    = (const float*)d_in[8];
    const float* c0v    = (const float*)d_in[9];
    const float* c1k    = (const float*)d_in[10];
    const float* c1v    = (const float*)d_in[11];

    float* out  = (float*)d_out;
    float* kout = out + (size_t)OUTSZ;
    float* vout = out + (size_t)2 * OUTSZ;

    dim3 g1(6, 120, 3);
    qkv_mma_kernel<<<g1, 256>>>(hidden, Wq, bq, Wk, bk, Wv, bv, kout, vout);

    attn_mma_kernel<<<B_ * NH_, 128>>>(kout, vout, c0k, c0v, c1k, c1v, mask, out);
}